// round 7
// baseline (speedup 1.0000x reference)
#include <cuda_runtime.h>
#include <math.h>

// Problem constants
#define BB 8
#define SS 2048
#define DD 1024
#define MTOT (BB*SS)          // 16384

// Scratch (static device memory; no allocations allowed)
__device__ float g_q[(size_t)MTOT * DD];            // 64 MB
__device__ float g_k[(size_t)MTOT * DD];            // 64 MB
__device__ float g_v[(size_t)MTOT * DD];            // 64 MB
__device__ float g_p[(size_t)BB * SS * SS];         // 128 MB (scores -> probs in place)

// ---------------------------------------------------------------------------
// Tiling parameters: 128x128 C-tile, K-tile 16, 256 threads, 8x8 per thread.
// ---------------------------------------------------------------------------
#define TBM 128
#define TBN 128
#define TBK 16
#define SPAD 132   // padded shared row stride (2-way instead of 4-way conflicts)

// ===========================================================================
// Kernel 1: QKV projection.  y = x @ W^T   (NT gemm)
//   A = x [MTOT, DD],  W[e,d] row-major -> B operand [N=DD, K=DD]
//   blockIdx.z selects (Wq->g_q, Wk->g_k, Wv->g_v)
// ===========================================================================
__global__ __launch_bounds__(256, 2)
void proj_kernel(const float* __restrict__ x,
                 const float* __restrict__ Wq,
                 const float* __restrict__ Wk,
                 const float* __restrict__ Wv)
{
    const float* W = (blockIdx.z == 0) ? Wq : (blockIdx.z == 1) ? Wk : Wv;
    float* O       = (blockIdx.z == 0) ? g_q : (blockIdx.z == 1) ? g_k : g_v;

    __shared__ float As[TBK][SPAD];
    __shared__ float Bs[TBK][SPAD];

    const int m0 = blockIdx.y * TBM;
    const int n0 = blockIdx.x * TBN;
    const int t  = threadIdx.x;
    const int tx = t & 15, ty = t >> 4;
    const int lr = t >> 2;          // 0..63
    const int lk = (t & 3) * 4;     // 0,4,8,12

    float acc[8][8];
    #pragma unroll
    for (int i = 0; i < 8; i++)
        #pragma unroll
        for (int j = 0; j < 8; j++) acc[i][j] = 0.f;

    const int K = DD;
    for (int k0 = 0; k0 < K; k0 += TBK) {
        #pragma unroll
        for (int r = 0; r < TBM; r += 64) {
            float4 va = *(const float4*)&x[(size_t)(m0 + lr + r) * K + k0 + lk];
            As[lk+0][lr+r] = va.x; As[lk+1][lr+r] = va.y;
            As[lk+2][lr+r] = va.z; As[lk+3][lr+r] = va.w;
            float4 vb = *(const float4*)&W[(size_t)(n0 + lr + r) * K + k0 + lk];
            Bs[lk+0][lr+r] = vb.x; Bs[lk+1][lr+r] = vb.y;
            Bs[lk+2][lr+r] = vb.z; Bs[lk+3][lr+r] = vb.w;
        }
        __syncthreads();
        #pragma unroll
        for (int kk = 0; kk < TBK; kk++) {
            float a[8], b[8];
            *(float4*)&a[0] = *(const float4*)&As[kk][ty*8];
            *(float4*)&a[4] = *(const float4*)&As[kk][ty*8+4];
            *(float4*)&b[0] = *(const float4*)&Bs[kk][tx*8];
            *(float4*)&b[4] = *(const float4*)&Bs[kk][tx*8+4];
            #pragma unroll
            for (int i = 0; i < 8; i++)
                #pragma unroll
                for (int j = 0; j < 8; j++)
                    acc[i][j] = fmaf(a[i], b[j], acc[i][j]);
        }
        __syncthreads();
    }
    #pragma unroll
    for (int i = 0; i < 8; i++) {
        size_t row = (size_t)(m0 + ty*8 + i);
        *(float4*)&O[row * DD + n0 + tx*8]     = make_float4(acc[i][0], acc[i][1], acc[i][2], acc[i][3]);
        *(float4*)&O[row * DD + n0 + tx*8 + 4] = make_float4(acc[i][4], acc[i][5], acc[i][6], acc[i][7]);
    }
}

// ===========================================================================
// Kernel 2: scores = q @ k^T per batch (NT gemm), causal tile skip.
// Raw (unscaled) scores written; scale applied in softmax.
// ===========================================================================
__global__ __launch_bounds__(256, 2)
void scores_kernel()
{
    const int m0 = blockIdx.y * TBM;
    const int n0 = blockIdx.x * TBN;
    if (n0 > m0 + TBM - 1) return;   // fully masked tile

    const int b = blockIdx.z;
    const float* A = g_q + (size_t)b * SS * DD;
    const float* Bm = g_k + (size_t)b * SS * DD;
    float* C = g_p + (size_t)b * SS * SS;

    __shared__ float As[TBK][SPAD];
    __shared__ float Bs[TBK][SPAD];

    const int t  = threadIdx.x;
    const int tx = t & 15, ty = t >> 4;
    const int lr = t >> 2;
    const int lk = (t & 3) * 4;

    float acc[8][8];
    #pragma unroll
    for (int i = 0; i < 8; i++)
        #pragma unroll
        for (int j = 0; j < 8; j++) acc[i][j] = 0.f;

    const int K = DD;
    for (int k0 = 0; k0 < K; k0 += TBK) {
        #pragma unroll
        for (int r = 0; r < TBM; r += 64) {
            float4 va = *(const float4*)&A[(size_t)(m0 + lr + r) * K + k0 + lk];
            As[lk+0][lr+r] = va.x; As[lk+1][lr+r] = va.y;
            As[lk+2][lr+r] = va.z; As[lk+3][lr+r] = va.w;
            float4 vb = *(const float4*)&Bm[(size_t)(n0 + lr + r) * K + k0 + lk];
            Bs[lk+0][lr+r] = vb.x; Bs[lk+1][lr+r] = vb.y;
            Bs[lk+2][lr+r] = vb.z; Bs[lk+3][lr+r] = vb.w;
        }
        __syncthreads();
        #pragma unroll
        for (int kk = 0; kk < TBK; kk++) {
            float a[8], bb[8];
            *(float4*)&a[0]  = *(const float4*)&As[kk][ty*8];
            *(float4*)&a[4]  = *(const float4*)&As[kk][ty*8+4];
            *(float4*)&bb[0] = *(const float4*)&Bs[kk][tx*8];
            *(float4*)&bb[4] = *(const float4*)&Bs[kk][tx*8+4];
            #pragma unroll
            for (int i = 0; i < 8; i++)
                #pragma unroll
                for (int j = 0; j < 8; j++)
                    acc[i][j] = fmaf(a[i], bb[j], acc[i][j]);
        }
        __syncthreads();
    }
    #pragma unroll
    for (int i = 0; i < 8; i++) {
        size_t row = (size_t)(m0 + ty*8 + i);
        *(float4*)&C[row * SS + n0 + tx*8]     = make_float4(acc[i][0], acc[i][1], acc[i][2], acc[i][3]);
        *(float4*)&C[row * SS + n0 + tx*8 + 4] = make_float4(acc[i][4], acc[i][5], acc[i][6], acc[i][7]);
    }
}

// ===========================================================================
// Kernel 3: causal row softmax, in place on g_p.
// Row i reads j in [0, i], writes probs, zero-fills (i, next 128-boundary)
// so the PV gemm can read full 128-wide K tiles.
// ===========================================================================
__device__ __forceinline__ float warpMax(float v) {
    #pragma unroll
    for (int o = 16; o > 0; o >>= 1) v = fmaxf(v, __shfl_xor_sync(0xffffffffu, v, o));
    return v;
}
__device__ __forceinline__ float warpSum(float v) {
    #pragma unroll
    for (int o = 16; o > 0; o >>= 1) v += __shfl_xor_sync(0xffffffffu, v, o);
    return v;
}

__global__ __launch_bounds__(256)
void softmax_kernel()
{
    __shared__ float smax[8];
    __shared__ float ssum[8];

    const int r = blockIdx.x;
    const int b = r / SS;
    const int i = r % SS;
    float* P = g_p + ((size_t)b * SS + i) * SS;
    const int len = i + 1;
    const float scale = 0.03125f;   // 1/sqrt(1024)

    const int t = threadIdx.x;
    const int lane = t & 31, w = t >> 5;

    float v[8];
    float m = -INFINITY;
    int cnt = 0;
    for (int j = t; j < len; j += 256) {
        float xv = P[j] * scale;
        v[cnt++] = xv;
        m = fmaxf(m, xv);
    }
    m = warpMax(m);
    if (lane == 0) smax[w] = m;
    __syncthreads();
    float mm = smax[0];
    #pragma unroll
    for (int q = 1; q < 8; q++) mm = fmaxf(mm, smax[q]);

    float sum = 0.f;
    #pragma unroll
    for (int q = 0; q < 8; q++) {
        int j = t + q * 256;
        if (j < len) {
            float e = __expf(v[q] - mm);
            v[q] = e;
            sum += e;
        }
    }
    sum = warpSum(sum);
    if (lane == 0) ssum[w] = sum;
    __syncthreads();
    float total = ssum[0];
    #pragma unroll
    for (int q = 1; q < 8; q++) total += ssum[q];
    const float inv = 1.f / total;

    cnt = 0;
    for (int j = t; j < len; j += 256) P[j] = v[cnt++] * inv;

    // zero-fill masked tail up to the 128-column tile boundary
    const int jend = ((i >> 7) + 1) << 7;
    for (int j = len + t; j < jend; j += 256) P[j] = 0.f;
}

// ===========================================================================
// Kernel 4: out = P @ V per batch (NN gemm), K-loop truncated at causal edge.
//   A = P [SS, SS], B = v [SS, DD], C = out [SS, DD]
// ===========================================================================
__global__ __launch_bounds__(256, 2)
void pv_kernel(float* __restrict__ out)
{
    const int b  = blockIdx.z;
    const int m0 = blockIdx.y * TBM;
    const int n0 = blockIdx.x * TBN;

    const float* A  = g_p + (size_t)b * SS * SS;
    const float* Bv = g_v + (size_t)b * SS * DD;
    float* C = out + (size_t)b * SS * DD;

    __shared__ float As[TBK][SPAD];
    __shared__ float Bs[TBK][SPAD];

    const int t  = threadIdx.x;
    const int tx = t & 15, ty = t >> 4;
    const int lr = t >> 2;          // A-load row helper
    const int lk = (t & 3) * 4;     // A-load k helper
    const int brow = t >> 5;        // 0..7   B-load row
    const int bcol = (t & 31) * 4;  // 0..124 B-load col

    float acc[8][8];
    #pragma unroll
    for (int i = 0; i < 8; i++)
        #pragma unroll
        for (int j = 0; j < 8; j++) acc[i][j] = 0.f;

    const int K = SS;
    const int kend = (m0 + TBM < K) ? (m0 + TBM) : K;   // causal bound

    for (int k0 = 0; k0 < kend; k0 += TBK) {
        #pragma unroll
        for (int r = 0; r < TBM; r += 64) {
            float4 va = *(const float4*)&A[(size_t)(m0 + lr + r) * K + k0 + lk];
            As[lk+0][lr+r] = va.x; As[lk+1][lr+r] = va.y;
            As[lk+2][lr+r] = va.z; As[lk+3][lr+r] = va.w;
        }
        #pragma unroll
        for (int r = 0; r < TBK; r += 8) {
            float4 vb = *(const float4*)&Bv[(size_t)(k0 + brow + r) * DD + n0 + bcol];
            *(float4*)&Bs[brow + r][bcol] = vb;
        }
        __syncthreads();
        #pragma unroll
        for (int kk = 0; kk < TBK; kk++) {
            float a[8], bb[8];
            *(float4*)&a[0]  = *(const float4*)&As[kk][ty*8];
            *(float4*)&a[4]  = *(const float4*)&As[kk][ty*8+4];
            *(float4*)&bb[0] = *(const float4*)&Bs[kk][tx*8];
            *(float4*)&bb[4] = *(const float4*)&Bs[kk][tx*8+4];
            #pragma unroll
            for (int i = 0; i < 8; i++)
                #pragma unroll
                for (int j = 0; j < 8; j++)
                    acc[i][j] = fmaf(a[i], bb[j], acc[i][j]);
        }
        __syncthreads();
    }
    #pragma unroll
    for (int i = 0; i < 8; i++) {
        size_t row = (size_t)(m0 + ty*8 + i);
        *(float4*)&C[row * DD + n0 + tx*8]     = make_float4(acc[i][0], acc[i][1], acc[i][2], acc[i][3]);
        *(float4*)&C[row * DD + n0 + tx*8 + 4] = make_float4(acc[i][4], acc[i][5], acc[i][6], acc[i][7]);
    }
}

// ===========================================================================
extern "C" void kernel_launch(void* const* d_in, const int* in_sizes, int n_in,
                              void* d_out, int out_size)
{
    (void)in_sizes; (void)n_in; (void)out_size;
    const float* x  = (const float*)d_in[0];
    const float* Wq = (const float*)d_in[1];
    const float* Wk = (const float*)d_in[2];
    const float* Wv = (const float*)d_in[3];
    float* out = (float*)d_out;

    dim3 gproj(DD / TBN, MTOT / TBM, 3);        // (8, 128, 3)
    proj_kernel<<<gproj, 256>>>(x, Wq, Wk, Wv);

    dim3 gsc(SS / TBN, SS / TBM, BB);           // (16, 16, 8)
    scores_kernel<<<gsc, 256>>>();

    softmax_kernel<<<MTOT, 256>>>();            // one block per row

    dim3 gpv(DD / TBN, SS / TBM, BB);           // (8, 16, 8)
    pv_kernel<<<gpv, 256>>>(out);
}

// round 8
// speedup vs baseline: 1.0003x; 1.0003x over previous
#include <cuda_runtime.h>
#include <math.h>

// Problem constants
#define BB 8
#define SS 2048
#define DD 1024
#define MTOT (BB*SS)          // 16384

// Scratch (static device memory; no allocations allowed)
__device__ float g_q[(size_t)MTOT * DD];            // 64 MB
__device__ float g_k[(size_t)MTOT * DD];            // 64 MB
__device__ float g_v[(size_t)MTOT * DD];            // 64 MB
__device__ float g_p[(size_t)BB * SS * SS];         // 128 MB (scores -> probs in place)

// ---------------------------------------------------------------------------
// Tiling parameters: 128x128 C-tile, K-tile 16, 256 threads, 8x8 per thread.
// ---------------------------------------------------------------------------
#define TBM 128
#define TBN 128
#define TBK 16
#define SPAD 132   // padded shared row stride (2-way instead of 4-way conflicts)

// ===========================================================================
// Kernel 1: QKV projection.  y = x @ W^T   (NT gemm)
//   A = x [MTOT, DD],  W[e,d] row-major -> B operand [N=DD, K=DD]
//   blockIdx.z selects (Wq->g_q, Wk->g_k, Wv->g_v)
// ===========================================================================
__global__ __launch_bounds__(256, 2)
void proj_kernel(const float* __restrict__ x,
                 const float* __restrict__ Wq,
                 const float* __restrict__ Wk,
                 const float* __restrict__ Wv)
{
    const float* W = (blockIdx.z == 0) ? Wq : (blockIdx.z == 1) ? Wk : Wv;
    float* O       = (blockIdx.z == 0) ? g_q : (blockIdx.z == 1) ? g_k : g_v;

    __shared__ float As[TBK][SPAD];
    __shared__ float Bs[TBK][SPAD];

    const int m0 = blockIdx.y * TBM;
    const int n0 = blockIdx.x * TBN;
    const int t  = threadIdx.x;
    const int tx = t & 15, ty = t >> 4;
    const int lr = t >> 2;          // 0..63
    const int lk = (t & 3) * 4;     // 0,4,8,12

    float acc[8][8];
    #pragma unroll
    for (int i = 0; i < 8; i++)
        #pragma unroll
        for (int j = 0; j < 8; j++) acc[i][j] = 0.f;

    const int K = DD;
    for (int k0 = 0; k0 < K; k0 += TBK) {
        #pragma unroll
        for (int r = 0; r < TBM; r += 64) {
            float4 va = *(const float4*)&x[(size_t)(m0 + lr + r) * K + k0 + lk];
            As[lk+0][lr+r] = va.x; As[lk+1][lr+r] = va.y;
            As[lk+2][lr+r] = va.z; As[lk+3][lr+r] = va.w;
            float4 vb = *(const float4*)&W[(size_t)(n0 + lr + r) * K + k0 + lk];
            Bs[lk+0][lr+r] = vb.x; Bs[lk+1][lr+r] = vb.y;
            Bs[lk+2][lr+r] = vb.z; Bs[lk+3][lr+r] = vb.w;
        }
        __syncthreads();
        #pragma unroll
        for (int kk = 0; kk < TBK; kk++) {
            float a[8], b[8];
            *(float4*)&a[0] = *(const float4*)&As[kk][ty*8];
            *(float4*)&a[4] = *(const float4*)&As[kk][ty*8+4];
            *(float4*)&b[0] = *(const float4*)&Bs[kk][tx*8];
            *(float4*)&b[4] = *(const float4*)&Bs[kk][tx*8+4];
            #pragma unroll
            for (int i = 0; i < 8; i++)
                #pragma unroll
                for (int j = 0; j < 8; j++)
                    acc[i][j] = fmaf(a[i], b[j], acc[i][j]);
        }
        __syncthreads();
    }
    #pragma unroll
    for (int i = 0; i < 8; i++) {
        size_t row = (size_t)(m0 + ty*8 + i);
        *(float4*)&O[row * DD + n0 + tx*8]     = make_float4(acc[i][0], acc[i][1], acc[i][2], acc[i][3]);
        *(float4*)&O[row * DD + n0 + tx*8 + 4] = make_float4(acc[i][4], acc[i][5], acc[i][6], acc[i][7]);
    }
}

// ===========================================================================
// Kernel 2: scores = q @ k^T per batch (NT gemm), causal tile skip.
// Raw (unscaled) scores written; scale applied in softmax.
// ===========================================================================
__global__ __launch_bounds__(256, 2)
void scores_kernel()
{
    const int m0 = blockIdx.y * TBM;
    const int n0 = blockIdx.x * TBN;
    if (n0 > m0 + TBM - 1) return;   // fully masked tile

    const int b = blockIdx.z;
    const float* A = g_q + (size_t)b * SS * DD;
    const float* Bm = g_k + (size_t)b * SS * DD;
    float* C = g_p + (size_t)b * SS * SS;

    __shared__ float As[TBK][SPAD];
    __shared__ float Bs[TBK][SPAD];

    const int t  = threadIdx.x;
    const int tx = t & 15, ty = t >> 4;
    const int lr = t >> 2;
    const int lk = (t & 3) * 4;

    float acc[8][8];
    #pragma unroll
    for (int i = 0; i < 8; i++)
        #pragma unroll
        for (int j = 0; j < 8; j++) acc[i][j] = 0.f;

    const int K = DD;
    for (int k0 = 0; k0 < K; k0 += TBK) {
        #pragma unroll
        for (int r = 0; r < TBM; r += 64) {
            float4 va = *(const float4*)&A[(size_t)(m0 + lr + r) * K + k0 + lk];
            As[lk+0][lr+r] = va.x; As[lk+1][lr+r] = va.y;
            As[lk+2][lr+r] = va.z; As[lk+3][lr+r] = va.w;
            float4 vb = *(const float4*)&Bm[(size_t)(n0 + lr + r) * K + k0 + lk];
            Bs[lk+0][lr+r] = vb.x; Bs[lk+1][lr+r] = vb.y;
            Bs[lk+2][lr+r] = vb.z; Bs[lk+3][lr+r] = vb.w;
        }
        __syncthreads();
        #pragma unroll
        for (int kk = 0; kk < TBK; kk++) {
            float a[8], bb[8];
            *(float4*)&a[0]  = *(const float4*)&As[kk][ty*8];
            *(float4*)&a[4]  = *(const float4*)&As[kk][ty*8+4];
            *(float4*)&bb[0] = *(const float4*)&Bs[kk][tx*8];
            *(float4*)&bb[4] = *(const float4*)&Bs[kk][tx*8+4];
            #pragma unroll
            for (int i = 0; i < 8; i++)
                #pragma unroll
                for (int j = 0; j < 8; j++)
                    acc[i][j] = fmaf(a[i], bb[j], acc[i][j]);
        }
        __syncthreads();
    }
    #pragma unroll
    for (int i = 0; i < 8; i++) {
        size_t row = (size_t)(m0 + ty*8 + i);
        *(float4*)&C[row * SS + n0 + tx*8]     = make_float4(acc[i][0], acc[i][1], acc[i][2], acc[i][3]);
        *(float4*)&C[row * SS + n0 + tx*8 + 4] = make_float4(acc[i][4], acc[i][5], acc[i][6], acc[i][7]);
    }
}

// ===========================================================================
// Kernel 3: causal row softmax, in place on g_p.
// Row i reads j in [0, i], writes probs, zero-fills (i, next 128-boundary)
// so the PV gemm can read full 128-wide K tiles.
// ===========================================================================
__device__ __forceinline__ float warpMax(float v) {
    #pragma unroll
    for (int o = 16; o > 0; o >>= 1) v = fmaxf(v, __shfl_xor_sync(0xffffffffu, v, o));
    return v;
}
__device__ __forceinline__ float warpSum(float v) {
    #pragma unroll
    for (int o = 16; o > 0; o >>= 1) v += __shfl_xor_sync(0xffffffffu, v, o);
    return v;
}

__global__ __launch_bounds__(256)
void softmax_kernel()
{
    __shared__ float smax[8];
    __shared__ float ssum[8];

    const int r = blockIdx.x;
    const int b = r / SS;
    const int i = r % SS;
    float* P = g_p + ((size_t)b * SS + i) * SS;
    const int len = i + 1;
    const float scale = 0.03125f;   // 1/sqrt(1024)

    const int t = threadIdx.x;
    const int lane = t & 31, w = t >> 5;

    float v[8];
    float m = -INFINITY;
    int cnt = 0;
    for (int j = t; j < len; j += 256) {
        float xv = P[j] * scale;
        v[cnt++] = xv;
        m = fmaxf(m, xv);
    }
    m = warpMax(m);
    if (lane == 0) smax[w] = m;
    __syncthreads();
    float mm = smax[0];
    #pragma unroll
    for (int q = 1; q < 8; q++) mm = fmaxf(mm, smax[q]);

    float sum = 0.f;
    #pragma unroll
    for (int q = 0; q < 8; q++) {
        int j = t + q * 256;
        if (j < len) {
            float e = __expf(v[q] - mm);
            v[q] = e;
            sum += e;
        }
    }
    sum = warpSum(sum);
    if (lane == 0) ssum[w] = sum;
    __syncthreads();
    float total = ssum[0];
    #pragma unroll
    for (int q = 1; q < 8; q++) total += ssum[q];
    const float inv = 1.f / total;

    cnt = 0;
    for (int j = t; j < len; j += 256) P[j] = v[cnt++] * inv;

    // zero-fill masked tail up to the 128-column tile boundary
    const int jend = ((i >> 7) + 1) << 7;
    for (int j = len + t; j < jend; j += 256) P[j] = 0.f;
}

// ===========================================================================
// Kernel 4: out = P @ V per batch (NN gemm), K-loop truncated at causal edge.
//   A = P [SS, SS], B = v [SS, DD], C = out [SS, DD]
// ===========================================================================
__global__ __launch_bounds__(256, 2)
void pv_kernel(float* __restrict__ out)
{
    const int b  = blockIdx.z;
    const int m0 = blockIdx.y * TBM;
    const int n0 = blockIdx.x * TBN;

    const float* A  = g_p + (size_t)b * SS * SS;
    const float* Bv = g_v + (size_t)b * SS * DD;
    float* C = out + (size_t)b * SS * DD;

    __shared__ float As[TBK][SPAD];
    __shared__ float Bs[TBK][SPAD];

    const int t  = threadIdx.x;
    const int tx = t & 15, ty = t >> 4;
    const int lr = t >> 2;          // A-load row helper
    const int lk = (t & 3) * 4;     // A-load k helper
    const int brow = t >> 5;        // 0..7   B-load row
    const int bcol = (t & 31) * 4;  // 0..124 B-load col

    float acc[8][8];
    #pragma unroll
    for (int i = 0; i < 8; i++)
        #pragma unroll
        for (int j = 0; j < 8; j++) acc[i][j] = 0.f;

    const int K = SS;
    const int kend = (m0 + TBM < K) ? (m0 + TBM) : K;   // causal bound

    for (int k0 = 0; k0 < kend; k0 += TBK) {
        #pragma unroll
        for (int r = 0; r < TBM; r += 64) {
            float4 va = *(const float4*)&A[(size_t)(m0 + lr + r) * K + k0 + lk];
            As[lk+0][lr+r] = va.x; As[lk+1][lr+r] = va.y;
            As[lk+2][lr+r] = va.z; As[lk+3][lr+r] = va.w;
        }
        #pragma unroll
        for (int r = 0; r < TBK; r += 8) {
            float4 vb = *(const float4*)&Bv[(size_t)(k0 + brow + r) * DD + n0 + bcol];
            *(float4*)&Bs[brow + r][bcol] = vb;
        }
        __syncthreads();
        #pragma unroll
        for (int kk = 0; kk < TBK; kk++) {
            float a[8], bb[8];
            *(float4*)&a[0]  = *(const float4*)&As[kk][ty*8];
            *(float4*)&a[4]  = *(const float4*)&As[kk][ty*8+4];
            *(float4*)&bb[0] = *(const float4*)&Bs[kk][tx*8];
            *(float4*)&bb[4] = *(const float4*)&Bs[kk][tx*8+4];
            #pragma unroll
            for (int i = 0; i < 8; i++)
                #pragma unroll
                for (int j = 0; j < 8; j++)
                    acc[i][j] = fmaf(a[i], bb[j], acc[i][j]);
        }
        __syncthreads();
    }
    #pragma unroll
    for (int i = 0; i < 8; i++) {
        size_t row = (size_t)(m0 + ty*8 + i);
        *(float4*)&C[row * DD + n0 + tx*8]     = make_float4(acc[i][0], acc[i][1], acc[i][2], acc[i][3]);
        *(float4*)&C[row * DD + n0 + tx*8 + 4] = make_float4(acc[i][4], acc[i][5], acc[i][6], acc[i][7]);
    }
}

// ===========================================================================
extern "C" void kernel_launch(void* const* d_in, const int* in_sizes, int n_in,
                              void* d_out, int out_size)
{
    (void)in_sizes; (void)n_in; (void)out_size;
    const float* x  = (const float*)d_in[0];
    const float* Wq = (const float*)d_in[1];
    const float* Wk = (const float*)d_in[2];
    const float* Wv = (const float*)d_in[3];
    float* out = (float*)d_out;

    dim3 gproj(DD / TBN, MTOT / TBM, 3);        // (8, 128, 3)
    proj_kernel<<<gproj, 256>>>(x, Wq, Wk, Wv);

    dim3 gsc(SS / TBN, SS / TBM, BB);           // (16, 16, 8)
    scores_kernel<<<gsc, 256>>>();

    softmax_kernel<<<MTOT, 256>>>();            // one block per row

    dim3 gpv(DD / TBN, SS / TBM, BB);           // (8, 16, 8)
    pv_kernel<<<gpv, 256>>>(out);
}

// round 9
// speedup vs baseline: 1.0012x; 1.0009x over previous
#include <cuda_runtime.h>
#include <math.h>

// Problem constants
#define BB 8
#define SS 2048
#define DD 1024
#define MTOT (BB*SS)          // 16384

// Scratch (static device memory; no allocations allowed)
__device__ float g_q[(size_t)MTOT * DD];            // 64 MB
__device__ float g_k[(size_t)MTOT * DD];            // 64 MB
__device__ float g_v[(size_t)MTOT * DD];            // 64 MB
__device__ float g_p[(size_t)BB * SS * SS];         // 128 MB (scores -> probs in place)

// ---------------------------------------------------------------------------
// Tiling parameters: 128x128 C-tile, K-tile 16, 256 threads, 8x8 per thread.
// ---------------------------------------------------------------------------
#define TBM 128
#define TBN 128
#define TBK 16
#define SPAD 132   // padded shared row stride (2-way instead of 4-way conflicts)

// ===========================================================================
// Kernel 1: QKV projection.  y = x @ W^T   (NT gemm)
//   A = x [MTOT, DD],  W[e,d] row-major -> B operand [N=DD, K=DD]
//   blockIdx.z selects (Wq->g_q, Wk->g_k, Wv->g_v)
// ===========================================================================
__global__ __launch_bounds__(256, 2)
void proj_kernel(const float* __restrict__ x,
                 const float* __restrict__ Wq,
                 const float* __restrict__ Wk,
                 const float* __restrict__ Wv)
{
    const float* W = (blockIdx.z == 0) ? Wq : (blockIdx.z == 1) ? Wk : Wv;
    float* O       = (blockIdx.z == 0) ? g_q : (blockIdx.z == 1) ? g_k : g_v;

    __shared__ float As[TBK][SPAD];
    __shared__ float Bs[TBK][SPAD];

    const int m0 = blockIdx.y * TBM;
    const int n0 = blockIdx.x * TBN;
    const int t  = threadIdx.x;
    const int tx = t & 15, ty = t >> 4;
    const int lr = t >> 2;          // 0..63
    const int lk = (t & 3) * 4;     // 0,4,8,12

    float acc[8][8];
    #pragma unroll
    for (int i = 0; i < 8; i++)
        #pragma unroll
        for (int j = 0; j < 8; j++) acc[i][j] = 0.f;

    const int K = DD;
    for (int k0 = 0; k0 < K; k0 += TBK) {
        #pragma unroll
        for (int r = 0; r < TBM; r += 64) {
            float4 va = *(const float4*)&x[(size_t)(m0 + lr + r) * K + k0 + lk];
            As[lk+0][lr+r] = va.x; As[lk+1][lr+r] = va.y;
            As[lk+2][lr+r] = va.z; As[lk+3][lr+r] = va.w;
            float4 vb = *(const float4*)&W[(size_t)(n0 + lr + r) * K + k0 + lk];
            Bs[lk+0][lr+r] = vb.x; Bs[lk+1][lr+r] = vb.y;
            Bs[lk+2][lr+r] = vb.z; Bs[lk+3][lr+r] = vb.w;
        }
        __syncthreads();
        #pragma unroll
        for (int kk = 0; kk < TBK; kk++) {
            float a[8], b[8];
            *(float4*)&a[0] = *(const float4*)&As[kk][ty*8];
            *(float4*)&a[4] = *(const float4*)&As[kk][ty*8+4];
            *(float4*)&b[0] = *(const float4*)&Bs[kk][tx*8];
            *(float4*)&b[4] = *(const float4*)&Bs[kk][tx*8+4];
            #pragma unroll
            for (int i = 0; i < 8; i++)
                #pragma unroll
                for (int j = 0; j < 8; j++)
                    acc[i][j] = fmaf(a[i], b[j], acc[i][j]);
        }
        __syncthreads();
    }
    #pragma unroll
    for (int i = 0; i < 8; i++) {
        size_t row = (size_t)(m0 + ty*8 + i);
        *(float4*)&O[row * DD + n0 + tx*8]     = make_float4(acc[i][0], acc[i][1], acc[i][2], acc[i][3]);
        *(float4*)&O[row * DD + n0 + tx*8 + 4] = make_float4(acc[i][4], acc[i][5], acc[i][6], acc[i][7]);
    }
}

// ===========================================================================
// Kernel 2: scores = q @ k^T per batch (NT gemm), causal tile skip.
// Raw (unscaled) scores written; scale applied in softmax.
// ===========================================================================
__global__ __launch_bounds__(256, 2)
void scores_kernel()
{
    const int m0 = blockIdx.y * TBM;
    const int n0 = blockIdx.x * TBN;
    if (n0 > m0 + TBM - 1) return;   // fully masked tile

    const int b = blockIdx.z;
    const float* A = g_q + (size_t)b * SS * DD;
    const float* Bm = g_k + (size_t)b * SS * DD;
    float* C = g_p + (size_t)b * SS * SS;

    __shared__ float As[TBK][SPAD];
    __shared__ float Bs[TBK][SPAD];

    const int t  = threadIdx.x;
    const int tx = t & 15, ty = t >> 4;
    const int lr = t >> 2;
    const int lk = (t & 3) * 4;

    float acc[8][8];
    #pragma unroll
    for (int i = 0; i < 8; i++)
        #pragma unroll
        for (int j = 0; j < 8; j++) acc[i][j] = 0.f;

    const int K = DD;
    for (int k0 = 0; k0 < K; k0 += TBK) {
        #pragma unroll
        for (int r = 0; r < TBM; r += 64) {
            float4 va = *(const float4*)&A[(size_t)(m0 + lr + r) * K + k0 + lk];
            As[lk+0][lr+r] = va.x; As[lk+1][lr+r] = va.y;
            As[lk+2][lr+r] = va.z; As[lk+3][lr+r] = va.w;
            float4 vb = *(const float4*)&Bm[(size_t)(n0 + lr + r) * K + k0 + lk];
            Bs[lk+0][lr+r] = vb.x; Bs[lk+1][lr+r] = vb.y;
            Bs[lk+2][lr+r] = vb.z; Bs[lk+3][lr+r] = vb.w;
        }
        __syncthreads();
        #pragma unroll
        for (int kk = 0; kk < TBK; kk++) {
            float a[8], bb[8];
            *(float4*)&a[0]  = *(const float4*)&As[kk][ty*8];
            *(float4*)&a[4]  = *(const float4*)&As[kk][ty*8+4];
            *(float4*)&bb[0] = *(const float4*)&Bs[kk][tx*8];
            *(float4*)&bb[4] = *(const float4*)&Bs[kk][tx*8+4];
            #pragma unroll
            for (int i = 0; i < 8; i++)
                #pragma unroll
                for (int j = 0; j < 8; j++)
                    acc[i][j] = fmaf(a[i], bb[j], acc[i][j]);
        }
        __syncthreads();
    }
    #pragma unroll
    for (int i = 0; i < 8; i++) {
        size_t row = (size_t)(m0 + ty*8 + i);
        *(float4*)&C[row * SS + n0 + tx*8]     = make_float4(acc[i][0], acc[i][1], acc[i][2], acc[i][3]);
        *(float4*)&C[row * SS + n0 + tx*8 + 4] = make_float4(acc[i][4], acc[i][5], acc[i][6], acc[i][7]);
    }
}

// ===========================================================================
// Kernel 3: causal row softmax, in place on g_p.
// Row i reads j in [0, i], writes probs, zero-fills (i, next 128-boundary)
// so the PV gemm can read full 128-wide K tiles.
// ===========================================================================
__device__ __forceinline__ float warpMax(float v) {
    #pragma unroll
    for (int o = 16; o > 0; o >>= 1) v = fmaxf(v, __shfl_xor_sync(0xffffffffu, v, o));
    return v;
}
__device__ __forceinline__ float warpSum(float v) {
    #pragma unroll
    for (int o = 16; o > 0; o >>= 1) v += __shfl_xor_sync(0xffffffffu, v, o);
    return v;
}

__global__ __launch_bounds__(256)
void softmax_kernel()
{
    __shared__ float smax[8];
    __shared__ float ssum[8];

    const int r = blockIdx.x;
    const int b = r / SS;
    const int i = r % SS;
    float* P = g_p + ((size_t)b * SS + i) * SS;
    const int len = i + 1;
    const float scale = 0.03125f;   // 1/sqrt(1024)

    const int t = threadIdx.x;
    const int lane = t & 31, w = t >> 5;

    float v[8];
    float m = -INFINITY;
    int cnt = 0;
    for (int j = t; j < len; j += 256) {
        float xv = P[j] * scale;
        v[cnt++] = xv;
        m = fmaxf(m, xv);
    }
    m = warpMax(m);
    if (lane == 0) smax[w] = m;
    __syncthreads();
    float mm = smax[0];
    #pragma unroll
    for (int q = 1; q < 8; q++) mm = fmaxf(mm, smax[q]);

    float sum = 0.f;
    #pragma unroll
    for (int q = 0; q < 8; q++) {
        int j = t + q * 256;
        if (j < len) {
            float e = __expf(v[q] - mm);
            v[q] = e;
            sum += e;
        }
    }
    sum = warpSum(sum);
    if (lane == 0) ssum[w] = sum;
    __syncthreads();
    float total = ssum[0];
    #pragma unroll
    for (int q = 1; q < 8; q++) total += ssum[q];
    const float inv = 1.f / total;

    cnt = 0;
    for (int j = t; j < len; j += 256) P[j] = v[cnt++] * inv;

    // zero-fill masked tail up to the 128-column tile boundary
    const int jend = ((i >> 7) + 1) << 7;
    for (int j = len + t; j < jend; j += 256) P[j] = 0.f;
}

// ===========================================================================
// Kernel 4: out = P @ V per batch (NN gemm), K-loop truncated at causal edge.
//   A = P [SS, SS], B = v [SS, DD], C = out [SS, DD]
// ===========================================================================
__global__ __launch_bounds__(256, 2)
void pv_kernel(float* __restrict__ out)
{
    const int b  = blockIdx.z;
    const int m0 = blockIdx.y * TBM;
    const int n0 = blockIdx.x * TBN;

    const float* A  = g_p + (size_t)b * SS * SS;
    const float* Bv = g_v + (size_t)b * SS * DD;
    float* C = out + (size_t)b * SS * DD;

    __shared__ float As[TBK][SPAD];
    __shared__ float Bs[TBK][SPAD];

    const int t  = threadIdx.x;
    const int tx = t & 15, ty = t >> 4;
    const int lr = t >> 2;          // A-load row helper
    const int lk = (t & 3) * 4;     // A-load k helper
    const int brow = t >> 5;        // 0..7   B-load row
    const int bcol = (t & 31) * 4;  // 0..124 B-load col

    float acc[8][8];
    #pragma unroll
    for (int i = 0; i < 8; i++)
        #pragma unroll
        for (int j = 0; j < 8; j++) acc[i][j] = 0.f;

    const int K = SS;
    const int kend = (m0 + TBM < K) ? (m0 + TBM) : K;   // causal bound

    for (int k0 = 0; k0 < kend; k0 += TBK) {
        #pragma unroll
        for (int r = 0; r < TBM; r += 64) {
            float4 va = *(const float4*)&A[(size_t)(m0 + lr + r) * K + k0 + lk];
            As[lk+0][lr+r] = va.x; As[lk+1][lr+r] = va.y;
            As[lk+2][lr+r] = va.z; As[lk+3][lr+r] = va.w;
        }
        #pragma unroll
        for (int r = 0; r < TBK; r += 8) {
            float4 vb = *(const float4*)&Bv[(size_t)(k0 + brow + r) * DD + n0 + bcol];
            *(float4*)&Bs[brow + r][bcol] = vb;
        }
        __syncthreads();
        #pragma unroll
        for (int kk = 0; kk < TBK; kk++) {
            float a[8], bb[8];
            *(float4*)&a[0]  = *(const float4*)&As[kk][ty*8];
            *(float4*)&a[4]  = *(const float4*)&As[kk][ty*8+4];
            *(float4*)&bb[0] = *(const float4*)&Bs[kk][tx*8];
            *(float4*)&bb[4] = *(const float4*)&Bs[kk][tx*8+4];
            #pragma unroll
            for (int i = 0; i < 8; i++)
                #pragma unroll
                for (int j = 0; j < 8; j++)
                    acc[i][j] = fmaf(a[i], bb[j], acc[i][j]);
        }
        __syncthreads();
    }
    #pragma unroll
    for (int i = 0; i < 8; i++) {
        size_t row = (size_t)(m0 + ty*8 + i);
        *(float4*)&C[row * DD + n0 + tx*8]     = make_float4(acc[i][0], acc[i][1], acc[i][2], acc[i][3]);
        *(float4*)&C[row * DD + n0 + tx*8 + 4] = make_float4(acc[i][4], acc[i][5], acc[i][6], acc[i][7]);
    }
}

// ===========================================================================
extern "C" void kernel_launch(void* const* d_in, const int* in_sizes, int n_in,
                              void* d_out, int out_size)
{
    (void)in_sizes; (void)n_in; (void)out_size;
    const float* x  = (const float*)d_in[0];
    const float* Wq = (const float*)d_in[1];
    const float* Wk = (const float*)d_in[2];
    const float* Wv = (const float*)d_in[3];
    float* out = (float*)d_out;

    dim3 gproj(DD / TBN, MTOT / TBM, 3);        // (8, 128, 3)
    proj_kernel<<<gproj, 256>>>(x, Wq, Wk, Wv);

    dim3 gsc(SS / TBN, SS / TBM, BB);           // (16, 16, 8)
    scores_kernel<<<gsc, 256>>>();

    softmax_kernel<<<MTOT, 256>>>();            // one block per row

    dim3 gpv(DD / TBN, SS / TBM, BB);           // (8, 16, 8)
    pv_kernel<<<gpv, 256>>>(out);
}

// round 10
// speedup vs baseline: 1.0017x; 1.0005x over previous
#include <cuda_runtime.h>
#include <math.h>

// Problem constants
#define BB 8
#define SS 2048
#define DD 1024
#define MTOT (BB*SS)          // 16384

// Scratch (static device memory; no allocations allowed)
__device__ float g_q[(size_t)MTOT * DD];            // 64 MB
__device__ float g_k[(size_t)MTOT * DD];            // 64 MB
__device__ float g_v[(size_t)MTOT * DD];            // 64 MB
__device__ float g_p[(size_t)BB * SS * SS];         // 128 MB (scores -> probs in place)

// ---------------------------------------------------------------------------
// Tiling parameters: 128x128 C-tile, K-tile 16, 256 threads, 8x8 per thread.
// ---------------------------------------------------------------------------
#define TBM 128
#define TBN 128
#define TBK 16
#define SPAD 132   // padded shared row stride (2-way instead of 4-way conflicts)

// ===========================================================================
// Kernel 1: QKV projection.  y = x @ W^T   (NT gemm)
//   A = x [MTOT, DD],  W[e,d] row-major -> B operand [N=DD, K=DD]
//   blockIdx.z selects (Wq->g_q, Wk->g_k, Wv->g_v)
// ===========================================================================
__global__ __launch_bounds__(256, 2)
void proj_kernel(const float* __restrict__ x,
                 const float* __restrict__ Wq,
                 const float* __restrict__ Wk,
                 const float* __restrict__ Wv)
{
    const float* W = (blockIdx.z == 0) ? Wq : (blockIdx.z == 1) ? Wk : Wv;
    float* O       = (blockIdx.z == 0) ? g_q : (blockIdx.z == 1) ? g_k : g_v;

    __shared__ float As[TBK][SPAD];
    __shared__ float Bs[TBK][SPAD];

    const int m0 = blockIdx.y * TBM;
    const int n0 = blockIdx.x * TBN;
    const int t  = threadIdx.x;
    const int tx = t & 15, ty = t >> 4;
    const int lr = t >> 2;          // 0..63
    const int lk = (t & 3) * 4;     // 0,4,8,12

    float acc[8][8];
    #pragma unroll
    for (int i = 0; i < 8; i++)
        #pragma unroll
        for (int j = 0; j < 8; j++) acc[i][j] = 0.f;

    const int K = DD;
    for (int k0 = 0; k0 < K; k0 += TBK) {
        #pragma unroll
        for (int r = 0; r < TBM; r += 64) {
            float4 va = *(const float4*)&x[(size_t)(m0 + lr + r) * K + k0 + lk];
            As[lk+0][lr+r] = va.x; As[lk+1][lr+r] = va.y;
            As[lk+2][lr+r] = va.z; As[lk+3][lr+r] = va.w;
            float4 vb = *(const float4*)&W[(size_t)(n0 + lr + r) * K + k0 + lk];
            Bs[lk+0][lr+r] = vb.x; Bs[lk+1][lr+r] = vb.y;
            Bs[lk+2][lr+r] = vb.z; Bs[lk+3][lr+r] = vb.w;
        }
        __syncthreads();
        #pragma unroll
        for (int kk = 0; kk < TBK; kk++) {
            float a[8], b[8];
            *(float4*)&a[0] = *(const float4*)&As[kk][ty*8];
            *(float4*)&a[4] = *(const float4*)&As[kk][ty*8+4];
            *(float4*)&b[0] = *(const float4*)&Bs[kk][tx*8];
            *(float4*)&b[4] = *(const float4*)&Bs[kk][tx*8+4];
            #pragma unroll
            for (int i = 0; i < 8; i++)
                #pragma unroll
                for (int j = 0; j < 8; j++)
                    acc[i][j] = fmaf(a[i], b[j], acc[i][j]);
        }
        __syncthreads();
    }
    #pragma unroll
    for (int i = 0; i < 8; i++) {
        size_t row = (size_t)(m0 + ty*8 + i);
        *(float4*)&O[row * DD + n0 + tx*8]     = make_float4(acc[i][0], acc[i][1], acc[i][2], acc[i][3]);
        *(float4*)&O[row * DD + n0 + tx*8 + 4] = make_float4(acc[i][4], acc[i][5], acc[i][6], acc[i][7]);
    }
}

// ===========================================================================
// Kernel 2: scores = q @ k^T per batch (NT gemm), causal tile skip.
// Raw (unscaled) scores written; scale applied in softmax.
// ===========================================================================
__global__ __launch_bounds__(256, 2)
void scores_kernel()
{
    const int m0 = blockIdx.y * TBM;
    const int n0 = blockIdx.x * TBN;
    if (n0 > m0 + TBM - 1) return;   // fully masked tile

    const int b = blockIdx.z;
    const float* A = g_q + (size_t)b * SS * DD;
    const float* Bm = g_k + (size_t)b * SS * DD;
    float* C = g_p + (size_t)b * SS * SS;

    __shared__ float As[TBK][SPAD];
    __shared__ float Bs[TBK][SPAD];

    const int t  = threadIdx.x;
    const int tx = t & 15, ty = t >> 4;
    const int lr = t >> 2;
    const int lk = (t & 3) * 4;

    float acc[8][8];
    #pragma unroll
    for (int i = 0; i < 8; i++)
        #pragma unroll
        for (int j = 0; j < 8; j++) acc[i][j] = 0.f;

    const int K = DD;
    for (int k0 = 0; k0 < K; k0 += TBK) {
        #pragma unroll
        for (int r = 0; r < TBM; r += 64) {
            float4 va = *(const float4*)&A[(size_t)(m0 + lr + r) * K + k0 + lk];
            As[lk+0][lr+r] = va.x; As[lk+1][lr+r] = va.y;
            As[lk+2][lr+r] = va.z; As[lk+3][lr+r] = va.w;
            float4 vb = *(const float4*)&Bm[(size_t)(n0 + lr + r) * K + k0 + lk];
            Bs[lk+0][lr+r] = vb.x; Bs[lk+1][lr+r] = vb.y;
            Bs[lk+2][lr+r] = vb.z; Bs[lk+3][lr+r] = vb.w;
        }
        __syncthreads();
        #pragma unroll
        for (int kk = 0; kk < TBK; kk++) {
            float a[8], bb[8];
            *(float4*)&a[0]  = *(const float4*)&As[kk][ty*8];
            *(float4*)&a[4]  = *(const float4*)&As[kk][ty*8+4];
            *(float4*)&bb[0] = *(const float4*)&Bs[kk][tx*8];
            *(float4*)&bb[4] = *(const float4*)&Bs[kk][tx*8+4];
            #pragma unroll
            for (int i = 0; i < 8; i++)
                #pragma unroll
                for (int j = 0; j < 8; j++)
                    acc[i][j] = fmaf(a[i], bb[j], acc[i][j]);
        }
        __syncthreads();
    }
    #pragma unroll
    for (int i = 0; i < 8; i++) {
        size_t row = (size_t)(m0 + ty*8 + i);
        *(float4*)&C[row * SS + n0 + tx*8]     = make_float4(acc[i][0], acc[i][1], acc[i][2], acc[i][3]);
        *(float4*)&C[row * SS + n0 + tx*8 + 4] = make_float4(acc[i][4], acc[i][5], acc[i][6], acc[i][7]);
    }
}

// ===========================================================================
// Kernel 3: causal row softmax, in place on g_p.
// Row i reads j in [0, i], writes probs, zero-fills (i, next 128-boundary)
// so the PV gemm can read full 128-wide K tiles.
// ===========================================================================
__device__ __forceinline__ float warpMax(float v) {
    #pragma unroll
    for (int o = 16; o > 0; o >>= 1) v = fmaxf(v, __shfl_xor_sync(0xffffffffu, v, o));
    return v;
}
__device__ __forceinline__ float warpSum(float v) {
    #pragma unroll
    for (int o = 16; o > 0; o >>= 1) v += __shfl_xor_sync(0xffffffffu, v, o);
    return v;
}

__global__ __launch_bounds__(256)
void softmax_kernel()
{
    __shared__ float smax[8];
    __shared__ float ssum[8];

    const int r = blockIdx.x;
    const int b = r / SS;
    const int i = r % SS;
    float* P = g_p + ((size_t)b * SS + i) * SS;
    const int len = i + 1;
    const float scale = 0.03125f;   // 1/sqrt(1024)

    const int t = threadIdx.x;
    const int lane = t & 31, w = t >> 5;

    float v[8];
    float m = -INFINITY;
    int cnt = 0;
    for (int j = t; j < len; j += 256) {
        float xv = P[j] * scale;
        v[cnt++] = xv;
        m = fmaxf(m, xv);
    }
    m = warpMax(m);
    if (lane == 0) smax[w] = m;
    __syncthreads();
    float mm = smax[0];
    #pragma unroll
    for (int q = 1; q < 8; q++) mm = fmaxf(mm, smax[q]);

    float sum = 0.f;
    #pragma unroll
    for (int q = 0; q < 8; q++) {
        int j = t + q * 256;
        if (j < len) {
            float e = __expf(v[q] - mm);
            v[q] = e;
            sum += e;
        }
    }
    sum = warpSum(sum);
    if (lane == 0) ssum[w] = sum;
    __syncthreads();
    float total = ssum[0];
    #pragma unroll
    for (int q = 1; q < 8; q++) total += ssum[q];
    const float inv = 1.f / total;

    cnt = 0;
    for (int j = t; j < len; j += 256) P[j] = v[cnt++] * inv;

    // zero-fill masked tail up to the 128-column tile boundary
    const int jend = ((i >> 7) + 1) << 7;
    for (int j = len + t; j < jend; j += 256) P[j] = 0.f;
}

// ===========================================================================
// Kernel 4: out = P @ V per batch (NN gemm), K-loop truncated at causal edge.
//   A = P [SS, SS], B = v [SS, DD], C = out [SS, DD]
// ===========================================================================
__global__ __launch_bounds__(256, 2)
void pv_kernel(float* __restrict__ out)
{
    const int b  = blockIdx.z;
    const int m0 = blockIdx.y * TBM;
    const int n0 = blockIdx.x * TBN;

    const float* A  = g_p + (size_t)b * SS * SS;
    const float* Bv = g_v + (size_t)b * SS * DD;
    float* C = out + (size_t)b * SS * DD;

    __shared__ float As[TBK][SPAD];
    __shared__ float Bs[TBK][SPAD];

    const int t  = threadIdx.x;
    const int tx = t & 15, ty = t >> 4;
    const int lr = t >> 2;          // A-load row helper
    const int lk = (t & 3) * 4;     // A-load k helper
    const int brow = t >> 5;        // 0..7   B-load row
    const int bcol = (t & 31) * 4;  // 0..124 B-load col

    float acc[8][8];
    #pragma unroll
    for (int i = 0; i < 8; i++)
        #pragma unroll
        for (int j = 0; j < 8; j++) acc[i][j] = 0.f;

    const int K = SS;
    const int kend = (m0 + TBM < K) ? (m0 + TBM) : K;   // causal bound

    for (int k0 = 0; k0 < kend; k0 += TBK) {
        #pragma unroll
        for (int r = 0; r < TBM; r += 64) {
            float4 va = *(const float4*)&A[(size_t)(m0 + lr + r) * K + k0 + lk];
            As[lk+0][lr+r] = va.x; As[lk+1][lr+r] = va.y;
            As[lk+2][lr+r] = va.z; As[lk+3][lr+r] = va.w;
        }
        #pragma unroll
        for (int r = 0; r < TBK; r += 8) {
            float4 vb = *(const float4*)&Bv[(size_t)(k0 + brow + r) * DD + n0 + bcol];
            *(float4*)&Bs[brow + r][bcol] = vb;
        }
        __syncthreads();
        #pragma unroll
        for (int kk = 0; kk < TBK; kk++) {
            float a[8], bb[8];
            *(float4*)&a[0]  = *(const float4*)&As[kk][ty*8];
            *(float4*)&a[4]  = *(const float4*)&As[kk][ty*8+4];
            *(float4*)&bb[0] = *(const float4*)&Bs[kk][tx*8];
            *(float4*)&bb[4] = *(const float4*)&Bs[kk][tx*8+4];
            #pragma unroll
            for (int i = 0; i < 8; i++)
                #pragma unroll
                for (int j = 0; j < 8; j++)
                    acc[i][j] = fmaf(a[i], bb[j], acc[i][j]);
        }
        __syncthreads();
    }
    #pragma unroll
    for (int i = 0; i < 8; i++) {
        size_t row = (size_t)(m0 + ty*8 + i);
        *(float4*)&C[row * DD + n0 + tx*8]     = make_float4(acc[i][0], acc[i][1], acc[i][2], acc[i][3]);
        *(float4*)&C[row * DD + n0 + tx*8 + 4] = make_float4(acc[i][4], acc[i][5], acc[i][6], acc[i][7]);
    }
}

// ===========================================================================
extern "C" void kernel_launch(void* const* d_in, const int* in_sizes, int n_in,
                              void* d_out, int out_size)
{
    (void)in_sizes; (void)n_in; (void)out_size;
    const float* x  = (const float*)d_in[0];
    const float* Wq = (const float*)d_in[1];
    const float* Wk = (const float*)d_in[2];
    const float* Wv = (const float*)d_in[3];
    float* out = (float*)d_out;

    dim3 gproj(DD / TBN, MTOT / TBM, 3);        // (8, 128, 3)
    proj_kernel<<<gproj, 256>>>(x, Wq, Wk, Wv);

    dim3 gsc(SS / TBN, SS / TBM, BB);           // (16, 16, 8)
    scores_kernel<<<gsc, 256>>>();

    softmax_kernel<<<MTOT, 256>>>();            // one block per row

    dim3 gpv(DD / TBN, SS / TBM, BB);           // (8, 16, 8)
    pv_kernel<<<gpv, 256>>>(out);
}

// round 11
// speedup vs baseline: 1.0046x; 1.0029x over previous
#include <cuda_runtime.h>
#include <math.h>

// Problem constants
#define BB 8
#define SS 2048
#define DD 1024
#define MTOT (BB*SS)          // 16384

// Scratch (static device memory; no allocations allowed)
__device__ float g_q[(size_t)MTOT * DD];            // 64 MB
__device__ float g_k[(size_t)MTOT * DD];            // 64 MB
__device__ float g_v[(size_t)MTOT * DD];            // 64 MB
__device__ float g_p[(size_t)BB * SS * SS];         // 128 MB (scores -> probs in place)

// ---------------------------------------------------------------------------
// Tiling parameters: 128x128 C-tile, K-tile 16, 256 threads, 8x8 per thread.
// ---------------------------------------------------------------------------
#define TBM 128
#define TBN 128
#define TBK 16
#define SPAD 132   // padded shared row stride (2-way instead of 4-way conflicts)

// ===========================================================================
// Kernel 1: QKV projection.  y = x @ W^T   (NT gemm)
//   A = x [MTOT, DD],  W[e,d] row-major -> B operand [N=DD, K=DD]
//   blockIdx.z selects (Wq->g_q, Wk->g_k, Wv->g_v)
// ===========================================================================
__global__ __launch_bounds__(256, 2)
void proj_kernel(const float* __restrict__ x,
                 const float* __restrict__ Wq,
                 const float* __restrict__ Wk,
                 const float* __restrict__ Wv)
{
    const float* W = (blockIdx.z == 0) ? Wq : (blockIdx.z == 1) ? Wk : Wv;
    float* O       = (blockIdx.z == 0) ? g_q : (blockIdx.z == 1) ? g_k : g_v;

    __shared__ float As[TBK][SPAD];
    __shared__ float Bs[TBK][SPAD];

    const int m0 = blockIdx.y * TBM;
    const int n0 = blockIdx.x * TBN;
    const int t  = threadIdx.x;
    const int tx = t & 15, ty = t >> 4;
    const int lr = t >> 2;          // 0..63
    const int lk = (t & 3) * 4;     // 0,4,8,12

    float acc[8][8];
    #pragma unroll
    for (int i = 0; i < 8; i++)
        #pragma unroll
        for (int j = 0; j < 8; j++) acc[i][j] = 0.f;

    const int K = DD;
    for (int k0 = 0; k0 < K; k0 += TBK) {
        #pragma unroll
        for (int r = 0; r < TBM; r += 64) {
            float4 va = *(const float4*)&x[(size_t)(m0 + lr + r) * K + k0 + lk];
            As[lk+0][lr+r] = va.x; As[lk+1][lr+r] = va.y;
            As[lk+2][lr+r] = va.z; As[lk+3][lr+r] = va.w;
            float4 vb = *(const float4*)&W[(size_t)(n0 + lr + r) * K + k0 + lk];
            Bs[lk+0][lr+r] = vb.x; Bs[lk+1][lr+r] = vb.y;
            Bs[lk+2][lr+r] = vb.z; Bs[lk+3][lr+r] = vb.w;
        }
        __syncthreads();
        #pragma unroll
        for (int kk = 0; kk < TBK; kk++) {
            float a[8], b[8];
            *(float4*)&a[0] = *(const float4*)&As[kk][ty*8];
            *(float4*)&a[4] = *(const float4*)&As[kk][ty*8+4];
            *(float4*)&b[0] = *(const float4*)&Bs[kk][tx*8];
            *(float4*)&b[4] = *(const float4*)&Bs[kk][tx*8+4];
            #pragma unroll
            for (int i = 0; i < 8; i++)
                #pragma unroll
                for (int j = 0; j < 8; j++)
                    acc[i][j] = fmaf(a[i], b[j], acc[i][j]);
        }
        __syncthreads();
    }
    #pragma unroll
    for (int i = 0; i < 8; i++) {
        size_t row = (size_t)(m0 + ty*8 + i);
        *(float4*)&O[row * DD + n0 + tx*8]     = make_float4(acc[i][0], acc[i][1], acc[i][2], acc[i][3]);
        *(float4*)&O[row * DD + n0 + tx*8 + 4] = make_float4(acc[i][4], acc[i][5], acc[i][6], acc[i][7]);
    }
}

// ===========================================================================
// Kernel 2: scores = q @ k^T per batch (NT gemm), causal tile skip.
// Raw (unscaled) scores written; scale applied in softmax.
// ===========================================================================
__global__ __launch_bounds__(256, 2)
void scores_kernel()
{
    const int m0 = blockIdx.y * TBM;
    const int n0 = blockIdx.x * TBN;
    if (n0 > m0 + TBM - 1) return;   // fully masked tile

    const int b = blockIdx.z;
    const float* A = g_q + (size_t)b * SS * DD;
    const float* Bm = g_k + (size_t)b * SS * DD;
    float* C = g_p + (size_t)b * SS * SS;

    __shared__ float As[TBK][SPAD];
    __shared__ float Bs[TBK][SPAD];

    const int t  = threadIdx.x;
    const int tx = t & 15, ty = t >> 4;
    const int lr = t >> 2;
    const int lk = (t & 3) * 4;

    float acc[8][8];
    #pragma unroll
    for (int i = 0; i < 8; i++)
        #pragma unroll
        for (int j = 0; j < 8; j++) acc[i][j] = 0.f;

    const int K = DD;
    for (int k0 = 0; k0 < K; k0 += TBK) {
        #pragma unroll
        for (int r = 0; r < TBM; r += 64) {
            float4 va = *(const float4*)&A[(size_t)(m0 + lr + r) * K + k0 + lk];
            As[lk+0][lr+r] = va.x; As[lk+1][lr+r] = va.y;
            As[lk+2][lr+r] = va.z; As[lk+3][lr+r] = va.w;
            float4 vb = *(const float4*)&Bm[(size_t)(n0 + lr + r) * K + k0 + lk];
            Bs[lk+0][lr+r] = vb.x; Bs[lk+1][lr+r] = vb.y;
            Bs[lk+2][lr+r] = vb.z; Bs[lk+3][lr+r] = vb.w;
        }
        __syncthreads();
        #pragma unroll
        for (int kk = 0; kk < TBK; kk++) {
            float a[8], bb[8];
            *(float4*)&a[0]  = *(const float4*)&As[kk][ty*8];
            *(float4*)&a[4]  = *(const float4*)&As[kk][ty*8+4];
            *(float4*)&bb[0] = *(const float4*)&Bs[kk][tx*8];
            *(float4*)&bb[4] = *(const float4*)&Bs[kk][tx*8+4];
            #pragma unroll
            for (int i = 0; i < 8; i++)
                #pragma unroll
                for (int j = 0; j < 8; j++)
                    acc[i][j] = fmaf(a[i], bb[j], acc[i][j]);
        }
        __syncthreads();
    }
    #pragma unroll
    for (int i = 0; i < 8; i++) {
        size_t row = (size_t)(m0 + ty*8 + i);
        *(float4*)&C[row * SS + n0 + tx*8]     = make_float4(acc[i][0], acc[i][1], acc[i][2], acc[i][3]);
        *(float4*)&C[row * SS + n0 + tx*8 + 4] = make_float4(acc[i][4], acc[i][5], acc[i][6], acc[i][7]);
    }
}

// ===========================================================================
// Kernel 3: causal row softmax, in place on g_p.
// Row i reads j in [0, i], writes probs, zero-fills (i, next 128-boundary)
// so the PV gemm can read full 128-wide K tiles.
// ===========================================================================
__device__ __forceinline__ float warpMax(float v) {
    #pragma unroll
    for (int o = 16; o > 0; o >>= 1) v = fmaxf(v, __shfl_xor_sync(0xffffffffu, v, o));
    return v;
}
__device__ __forceinline__ float warpSum(float v) {
    #pragma unroll
    for (int o = 16; o > 0; o >>= 1) v += __shfl_xor_sync(0xffffffffu, v, o);
    return v;
}

__global__ __launch_bounds__(256)
void softmax_kernel()
{
    __shared__ float smax[8];
    __shared__ float ssum[8];

    const int r = blockIdx.x;
    const int b = r / SS;
    const int i = r % SS;
    float* P = g_p + ((size_t)b * SS + i) * SS;
    const int len = i + 1;
    const float scale = 0.03125f;   // 1/sqrt(1024)

    const int t = threadIdx.x;
    const int lane = t & 31, w = t >> 5;

    float v[8];
    float m = -INFINITY;
    int cnt = 0;
    for (int j = t; j < len; j += 256) {
        float xv = P[j] * scale;
        v[cnt++] = xv;
        m = fmaxf(m, xv);
    }
    m = warpMax(m);
    if (lane == 0) smax[w] = m;
    __syncthreads();
    float mm = smax[0];
    #pragma unroll
    for (int q = 1; q < 8; q++) mm = fmaxf(mm, smax[q]);

    float sum = 0.f;
    #pragma unroll
    for (int q = 0; q < 8; q++) {
        int j = t + q * 256;
        if (j < len) {
            float e = __expf(v[q] - mm);
            v[q] = e;
            sum += e;
        }
    }
    sum = warpSum(sum);
    if (lane == 0) ssum[w] = sum;
    __syncthreads();
    float total = ssum[0];
    #pragma unroll
    for (int q = 1; q < 8; q++) total += ssum[q];
    const float inv = 1.f / total;

    cnt = 0;
    for (int j = t; j < len; j += 256) P[j] = v[cnt++] * inv;

    // zero-fill masked tail up to the 128-column tile boundary
    const int jend = ((i >> 7) + 1) << 7;
    for (int j = len + t; j < jend; j += 256) P[j] = 0.f;
}

// ===========================================================================
// Kernel 4: out = P @ V per batch (NN gemm), K-loop truncated at causal edge.
//   A = P [SS, SS], B = v [SS, DD], C = out [SS, DD]
// ===========================================================================
__global__ __launch_bounds__(256, 2)
void pv_kernel(float* __restrict__ out)
{
    const int b  = blockIdx.z;
    const int m0 = blockIdx.y * TBM;
    const int n0 = blockIdx.x * TBN;

    const float* A  = g_p + (size_t)b * SS * SS;
    const float* Bv = g_v + (size_t)b * SS * DD;
    float* C = out + (size_t)b * SS * DD;

    __shared__ float As[TBK][SPAD];
    __shared__ float Bs[TBK][SPAD];

    const int t  = threadIdx.x;
    const int tx = t & 15, ty = t >> 4;
    const int lr = t >> 2;          // A-load row helper
    const int lk = (t & 3) * 4;     // A-load k helper
    const int brow = t >> 5;        // 0..7   B-load row
    const int bcol = (t & 31) * 4;  // 0..124 B-load col

    float acc[8][8];
    #pragma unroll
    for (int i = 0; i < 8; i++)
        #pragma unroll
        for (int j = 0; j < 8; j++) acc[i][j] = 0.f;

    const int K = SS;
    const int kend = (m0 + TBM < K) ? (m0 + TBM) : K;   // causal bound

    for (int k0 = 0; k0 < kend; k0 += TBK) {
        #pragma unroll
        for (int r = 0; r < TBM; r += 64) {
            float4 va = *(const float4*)&A[(size_t)(m0 + lr + r) * K + k0 + lk];
            As[lk+0][lr+r] = va.x; As[lk+1][lr+r] = va.y;
            As[lk+2][lr+r] = va.z; As[lk+3][lr+r] = va.w;
        }
        #pragma unroll
        for (int r = 0; r < TBK; r += 8) {
            float4 vb = *(const float4*)&Bv[(size_t)(k0 + brow + r) * DD + n0 + bcol];
            *(float4*)&Bs[brow + r][bcol] = vb;
        }
        __syncthreads();
        #pragma unroll
        for (int kk = 0; kk < TBK; kk++) {
            float a[8], bb[8];
            *(float4*)&a[0]  = *(const float4*)&As[kk][ty*8];
            *(float4*)&a[4]  = *(const float4*)&As[kk][ty*8+4];
            *(float4*)&bb[0] = *(const float4*)&Bs[kk][tx*8];
            *(float4*)&bb[4] = *(const float4*)&Bs[kk][tx*8+4];
            #pragma unroll
            for (int i = 0; i < 8; i++)
                #pragma unroll
                for (int j = 0; j < 8; j++)
                    acc[i][j] = fmaf(a[i], bb[j], acc[i][j]);
        }
        __syncthreads();
    }
    #pragma unroll
    for (int i = 0; i < 8; i++) {
        size_t row = (size_t)(m0 + ty*8 + i);
        *(float4*)&C[row * DD + n0 + tx*8]     = make_float4(acc[i][0], acc[i][1], acc[i][2], acc[i][3]);
        *(float4*)&C[row * DD + n0 + tx*8 + 4] = make_float4(acc[i][4], acc[i][5], acc[i][6], acc[i][7]);
    }
}

// ===========================================================================
extern "C" void kernel_launch(void* const* d_in, const int* in_sizes, int n_in,
                              void* d_out, int out_size)
{
    (void)in_sizes; (void)n_in; (void)out_size;
    const float* x  = (const float*)d_in[0];
    const float* Wq = (const float*)d_in[1];
    const float* Wk = (const float*)d_in[2];
    const float* Wv = (const float*)d_in[3];
    float* out = (float*)d_out;

    dim3 gproj(DD / TBN, MTOT / TBM, 3);        // (8, 128, 3)
    proj_kernel<<<gproj, 256>>>(x, Wq, Wk, Wv);

    dim3 gsc(SS / TBN, SS / TBM, BB);           // (16, 16, 8)
    scores_kernel<<<gsc, 256>>>();

    softmax_kernel<<<MTOT, 256>>>();            // one block per row

    dim3 gpv(DD / TBN, SS / TBM, BB);           // (8, 16, 8)
    pv_kernel<<<gpv, 256>>>(out);
}